// round 15
// baseline (speedup 1.0000x reference)
#include <cuda_runtime.h>

namespace {
constexpr int NN   = 24;
constexpr int FIN  = 7;
constexpr int WD   = 64;
constexpr int FOUT = 13;
constexpr int TB   = 8;    // batch tile per CTA, single-buffered, 3 CTAs/SM
constexpr int NT   = 384;  // 24 nodes x 16 o-groups
constexpr int STATE = NN * WD;
}

// SMPL tree adjacency CSR (self + parent + children)
__constant__ int c_nbr_off[25] = {0,4,7,10,13,16,19,22,25,28,33,35,37,40,43,46,48,51,54,57,60,63,66,68,70};
__constant__ int c_nbr_lst[70] = {
    0,1,2,3, 1,0,4, 2,0,5, 3,0,6, 4,1,7, 5,2,8, 6,3,9, 7,4,10, 8,5,11,
    9,6,12,13,14, 10,7, 11,8, 12,9,15, 13,9,16, 14,9,17, 15,12, 16,13,18,
    17,14,19, 18,16,20, 19,17,21, 20,18,22, 21,19,23, 22,20, 23,21
};
__constant__ int c_nbr_m[70] = {
    0,0,0,0, 1,1,1, 2,2,2, 3,3,3, 4,4,4, 5,5,5, 6,6,6, 7,7,7, 8,8,8,
    9,9,9,9,9, 10,10, 11,11, 12,12,12, 13,13,13, 14,14,14, 15,15, 16,16,16,
    17,17,17, 18,18,18, 19,19,19, 20,20,20, 21,21,21, 22,22, 23,23
};

// packed 2xfp32 helpers (Blackwell f32x2; PTX-only)
__device__ __forceinline__ unsigned long long dup2(float s) {
    unsigned long long d;
    asm("mov.b64 %0, {%1, %1};" : "=l"(d) : "r"(__float_as_uint(s)));
    return d;
}
__device__ __forceinline__ void fma2(unsigned long long& d,
                                     unsigned long long a, unsigned long long b) {
    asm("fma.rn.f32x2 %0, %1, %2, %0;" : "+l"(d) : "l"(a), "l"(b));
}

__global__ __launch_bounds__(NT, 3)
void gnn_fused(const float* __restrict__ x,
               const float* __restrict__ w0, const float* __restrict__ w1,
               const float* __restrict__ w2, const float* __restrict__ w3,
               const float* __restrict__ aw0, const float* __restrict__ aw1,
               const float* __restrict__ aw2, const float* __restrict__ aw3,
               const float* __restrict__ b0, const float* __restrict__ b1,
               const float* __restrict__ b2, const float* __restrict__ b3,
               float* __restrict__ out, int B)
{
    extern __shared__ float smem[];
    float* S    = smem;                 // TB*STATE (single state buffer)
    float* X    = S + TB * STATE;       // TB*NN*FOUT (xin staging / L3 out)
    float* aeff = X + TB * NN * FOUT;   // 4*70
    float* bias = aeff + 4 * 70;        // 3*64 + 13

    const int tid = threadIdx.x;
    const long brow0 = (long)blockIdx.x * TB;

    // ---- stage constants + masked input ----
    for (int idx = tid; idx < 4 * 70; idx += NT) {
        int l = idx / 70, e = idx - l * 70;
        const float* aw = (l == 0) ? aw0 : (l == 1) ? aw1 : (l == 2) ? aw2 : aw3;
        aeff[idx] = aw[c_nbr_m[e] * NN + c_nbr_lst[e]];
    }
    for (int idx = tid; idx < 3 * WD + FOUT; idx += NT) {
        float v;
        if      (idx <     WD) v = b0[idx];
        else if (idx < 2 * WD) v = b1[idx - WD];
        else if (idx < 3 * WD) v = b2[idx - 2 * WD];
        else                   v = b3[idx - 3 * WD];
        bias[idx] = v;
    }
    for (int idx = tid; idx < TB * NN * FIN; idx += NT) {
        const int bl = idx / (NN * FIN);
        const int j  = idx % (NN * FIN);
        float v = 0.0f;
        if (brow0 + bl < B && j >= FIN)   // root joint masked
            v = x[(brow0 + bl) * (NN * FIN) + j];
        X[idx] = v;
    }
    __syncthreads();

    const int n  = tid >> 4;        // node 0..23
    const int o0 = (tid & 15) * 4;  // output feature group

    // ---- Layer 0 matmul: X(xin) @ w0 -> S ----
    {
        float4 acc[TB];
        #pragma unroll
        for (int b = 0; b < TB; b++) acc[b] = make_float4(0.f, 0.f, 0.f, 0.f);
        #pragma unroll
        for (int i = 0; i < FIN; i++) {
            const float4 wv = __ldg(reinterpret_cast<const float4*>(w0 + (n * FIN + i) * WD + o0));
            #pragma unroll
            for (int b = 0; b < TB; b++) {
                const float xv = X[b * (NN * FIN) + n * FIN + i];
                acc[b].x = fmaf(xv, wv.x, acc[b].x);
                acc[b].y = fmaf(xv, wv.y, acc[b].y);
                acc[b].z = fmaf(xv, wv.z, acc[b].z);
                acc[b].w = fmaf(xv, wv.w, acc[b].w);
            }
        }
        #pragma unroll
        for (int b = 0; b < TB; b++)
            *reinterpret_cast<float4*>(S + b * STATE + n * WD + o0) = acc[b];
    }
    __syncthreads();

    // ---- In-place sparse tree aggregation + bias + ReLU on S ----
    // Batch quads: all reads of quad q complete (barrier) before quad q's rows
    // are overwritten; later quads touch disjoint batch rows.
    auto agg = [&](const float* __restrict__ ae, const float* __restrict__ bi) {
        const int s = c_nbr_off[n], e = c_nbr_off[n + 1];
        const float4 bv = make_float4(bi[o0], bi[o0 + 1], bi[o0 + 2], bi[o0 + 3]);
        #pragma unroll
        for (int bq = 0; bq < TB; bq += 4) {
            float4 a[4];
            #pragma unroll
            for (int q = 0; q < 4; q++) a[q] = bv;
            for (int k = s; k < e; k++) {
                const float aw = ae[k];
                const float* hp = S + c_nbr_lst[k] * WD + o0;
                #pragma unroll
                for (int q = 0; q < 4; q++) {
                    const float4 h = *reinterpret_cast<const float4*>(hp + (bq + q) * STATE);
                    a[q].x = fmaf(aw, h.x, a[q].x);
                    a[q].y = fmaf(aw, h.y, a[q].y);
                    a[q].z = fmaf(aw, h.z, a[q].z);
                    a[q].w = fmaf(aw, h.w, a[q].w);
                }
            }
            __syncthreads();   // reads of quad bq done CTA-wide
            float* dp = S + n * WD + o0;
            #pragma unroll
            for (int q = 0; q < 4; q++) {
                a[q].x = fmaxf(a[q].x, 0.f); a[q].y = fmaxf(a[q].y, 0.f);
                a[q].z = fmaxf(a[q].z, 0.f); a[q].w = fmaxf(a[q].w, 0.f);
                *reinterpret_cast<float4*>(dp + (bq + q) * STATE) = a[q];
            }
            __syncthreads();   // writes visible before next quad / next phase
        }
    };

    // ---- In-place hidden matmul (node-local), f32x2, i-step 2 (lean regs) ----
    auto mm64 = [&](const float* __restrict__ wgt) {
        unsigned long long accL[TB], accH[TB];
        #pragma unroll
        for (int b = 0; b < TB; b++) { accL[b] = 0ull; accH[b] = 0ull; }
        const float* wrow = wgt + n * WD * WD + o0;
        const float* abase = S + n * WD;
        #pragma unroll 4
        for (int i = 0; i < WD; i += 2) {
            const ulonglong2 wp0 = __ldg(reinterpret_cast<const ulonglong2*>(wrow + (i + 0) * WD));
            const ulonglong2 wp1 = __ldg(reinterpret_cast<const ulonglong2*>(wrow + (i + 1) * WD));
            #pragma unroll
            for (int b = 0; b < TB; b++) {
                const float2 xv = *reinterpret_cast<const float2*>(abase + b * STATE + i);
                const unsigned long long x0 = dup2(xv.x);
                fma2(accL[b], x0, wp0.x);
                fma2(accH[b], x0, wp0.y);
                const unsigned long long x1 = dup2(xv.y);
                fma2(accL[b], x1, wp1.x);
                fma2(accH[b], x1, wp1.y);
            }
        }
        __syncthreads();   // all reads of S complete CTA-wide
        #pragma unroll
        for (int b = 0; b < TB; b++)
            *reinterpret_cast<ulonglong2*>(S + b * STATE + n * WD + o0) =
                make_ulonglong2(accL[b], accH[b]);
        __syncthreads();
    };

    agg(aeff + 0,   bias + 0);        // L0 agg (+relu)
    mm64(w1);                          // L1 matmul
    agg(aeff + 70,  bias + WD);       // L1 agg (+relu)
    mm64(w2);                          // L2 matmul
    agg(aeff + 140, bias + 2 * WD);   // L2 agg (+relu)

    // ---- Layer 3 matmul: S @ w3 -> X[b][n][13] ----
    if (tid < NN * FOUT) {
        const int n3 = tid / FOUT, o3 = tid - n3 * FOUT;
        float acc[TB];
        #pragma unroll
        for (int b = 0; b < TB; b++) acc[b] = 0.f;
        #pragma unroll 4
        for (int i = 0; i < WD; i++) {
            const float wv = __ldg(w3 + (n3 * WD + i) * FOUT + o3);
            #pragma unroll
            for (int b = 0; b < TB; b++)
                acc[b] = fmaf(S[b * STATE + n3 * WD + i], wv, acc[b]);
        }
        #pragma unroll
        for (int b = 0; b < TB; b++)
            X[b * (NN * FOUT) + n3 * FOUT + o3] = acc[b];
    }
    __syncthreads();

    // ---- Layer 3 aggregation + bias, store to global (guarded) ----
    if (tid < NN * FOUT) {
        const int n3 = tid / FOUT, o3 = tid - n3 * FOUT;
        const int s = c_nbr_off[n3], e = c_nbr_off[n3 + 1];
        const float bv3 = bias[3 * WD + o3];
        #pragma unroll
        for (int b = 0; b < TB; b++) {
            float a0 = bv3;
            for (int k = s; k < e; k++)
                a0 = fmaf(aeff[210 + k], X[b * (NN * FOUT) + c_nbr_lst[k] * FOUT + o3], a0);
            if (brow0 + b < B)
                out[(brow0 + b) * (NN * FOUT) + n3 * FOUT + o3] = a0;
        }
    }
}

extern "C" void kernel_launch(void* const* d_in, const int* in_sizes, int n_in,
                              void* d_out, int out_size) {
    const float* x   = (const float*)d_in[0];
    const float* w0  = (const float*)d_in[1];
    const float* w1  = (const float*)d_in[2];
    const float* w2  = (const float*)d_in[3];
    const float* w3  = (const float*)d_in[4];
    const float* aw0 = (const float*)d_in[5];
    const float* aw1 = (const float*)d_in[6];
    const float* aw2 = (const float*)d_in[7];
    const float* aw3 = (const float*)d_in[8];
    const float* b0  = (const float*)d_in[9];
    const float* b1  = (const float*)d_in[10];
    const float* b2  = (const float*)d_in[11];
    const float* b3  = (const float*)d_in[12];
    float* out = (float*)d_out;

    const int B = in_sizes[0] / (NN * FIN);
    const int grid = (B + TB - 1) / TB;
    const size_t smem_bytes =
        (size_t)(TB * STATE + TB * NN * FOUT + 4 * 70 + 3 * WD + FOUT) * sizeof(float);

    cudaFuncSetAttribute(gnn_fused, cudaFuncAttributeMaxDynamicSharedMemorySize,
                         (int)smem_bytes);
    gnn_fused<<<grid, NT, smem_bytes>>>(x, w0, w1, w2, w3,
                                        aw0, aw1, aw2, aw3,
                                        b0, b1, b2, b3, out, B);
}

// round 16
// speedup vs baseline: 1.8403x; 1.8403x over previous
#include <cuda_runtime.h>

namespace {
constexpr int NN   = 24;   // nodes
constexpr int FIN  = 7;    // input features
constexpr int WD   = 64;   // hidden width
constexpr int FOUT = 13;   // output features
constexpr int TB   = 6;    // batch tile per CTA (3 CTAs/SM)
constexpr int NT   = 384;  // 24 nodes * 16 o-groups
constexpr int STATE = NN * WD;  // 1536 floats per batch row
}

// SMPL tree adjacency CSR (self + parent + children)
__constant__ int c_nbr_off[25] = {0,4,7,10,13,16,19,22,25,28,33,35,37,40,43,46,48,51,54,57,60,63,66,68,70};
__constant__ int c_nbr_lst[70] = {
    0,1,2,3, 1,0,4, 2,0,5, 3,0,6, 4,1,7, 5,2,8, 6,3,9, 7,4,10, 8,5,11,
    9,6,12,13,14, 10,7, 11,8, 12,9,15, 13,9,16, 14,9,17, 15,12, 16,13,18,
    17,14,19, 18,16,20, 19,17,21, 20,18,22, 21,19,23, 22,20, 23,21
};
__constant__ int c_nbr_m[70] = {
    0,0,0,0, 1,1,1, 2,2,2, 3,3,3, 4,4,4, 5,5,5, 6,6,6, 7,7,7, 8,8,8,
    9,9,9,9,9, 10,10, 11,11, 12,12,12, 13,13,13, 14,14,14, 15,15, 16,16,16,
    17,17,17, 18,18,18, 19,19,19, 20,20,20, 21,21,21, 22,22, 23,23
};

// packed 2xfp32 helpers (Blackwell f32x2; PTX-only)
__device__ __forceinline__ unsigned long long dup2(float s) {
    unsigned long long d;
    asm("mov.b64 %0, {%1, %1};" : "=l"(d) : "r"(__float_as_uint(s)));
    return d;
}
__device__ __forceinline__ void fma2(unsigned long long& d,
                                     unsigned long long a, unsigned long long b) {
    asm("fma.rn.f32x2 %0, %1, %2, %0;" : "+l"(d) : "l"(a), "l"(b));
}

__global__ __launch_bounds__(NT, 3)
void gnn_fused(const float* __restrict__ x,
               const float* __restrict__ w0, const float* __restrict__ w1,
               const float* __restrict__ w2, const float* __restrict__ w3,
               const float* __restrict__ aw0, const float* __restrict__ aw1,
               const float* __restrict__ aw2, const float* __restrict__ aw3,
               const float* __restrict__ b0, const float* __restrict__ b1,
               const float* __restrict__ b2, const float* __restrict__ b3,
               float* __restrict__ out, int B)
{
    extern __shared__ float smem[];
    float* bufA = smem;                    // TB*STATE floats
    float* bufB = bufA + TB * STATE;       // TB*STATE
    float* xin  = bufB;                    // alias: xin dead once L0 agg writes bufB
    float* aeff = bufB + TB * STATE;       // 4*70 masked adjacency weights
    float* bias = aeff + 4 * 70;           // 3*64 + 13

    const int tid = threadIdx.x;
    const long brow0 = (long)blockIdx.x * TB;

    // Stage masked adjacency weights (adjw * adj, nonzeros only)
    for (int idx = tid; idx < 4 * 70; idx += NT) {
        int l = idx / 70, e = idx - l * 70;
        const float* aw = (l == 0) ? aw0 : (l == 1) ? aw1 : (l == 2) ? aw2 : aw3;
        aeff[idx] = aw[c_nbr_m[e] * NN + c_nbr_lst[e]];
    }
    // Stage biases
    for (int idx = tid; idx < 3 * WD + FOUT; idx += NT) {
        float v;
        if      (idx <     WD) v = b0[idx];
        else if (idx < 2 * WD) v = b1[idx - WD];
        else if (idx < 3 * WD) v = b2[idx - 2 * WD];
        else                   v = b3[idx - 3 * WD];
        bias[idx] = v;
    }
    // Stage input tile with root-node mask; guard the B-remainder tile
    for (int idx = tid; idx < TB * NN * FIN; idx += NT) {
        const int bl = idx / (NN * FIN);
        const int j  = idx % (NN * FIN);
        float v = 0.0f;
        if (brow0 + bl < B && j >= FIN)   // node 0 masked
            v = x[(brow0 + bl) * (NN * FIN) + j];
        xin[idx] = v;
    }
    __syncthreads();

    const int n  = tid >> 4;        // node 0..23
    const int o0 = (tid & 15) * 4;  // output feature group

    // ---- Layer 0 matmul: xin[b][n][0:7] @ w0[n][7][64] -> bufA ----
    {
        float4 acc[TB];
        #pragma unroll
        for (int b = 0; b < TB; b++) acc[b] = make_float4(0.f, 0.f, 0.f, 0.f);
        #pragma unroll
        for (int i = 0; i < FIN; i++) {
            const float4 wv = __ldg(reinterpret_cast<const float4*>(w0 + (n * FIN + i) * WD + o0));
            #pragma unroll
            for (int b = 0; b < TB; b++) {
                const float xv = xin[b * (NN * FIN) + n * FIN + i];
                acc[b].x = fmaf(xv, wv.x, acc[b].x);
                acc[b].y = fmaf(xv, wv.y, acc[b].y);
                acc[b].z = fmaf(xv, wv.z, acc[b].z);
                acc[b].w = fmaf(xv, wv.w, acc[b].w);
            }
        }
        __syncthreads();   // xin reads done (xin aliases bufB)
        #pragma unroll
        for (int b = 0; b < TB; b++)
            *reinterpret_cast<float4*>(bufA + b * STATE + n * WD + o0) = acc[b];
    }
    __syncthreads();

    // Sparse tree aggregation + bias (+ReLU): h -> dst
    auto agg = [&](const float* __restrict__ h, const float* __restrict__ ae,
                   const float* __restrict__ bi, float* __restrict__ dst, bool relu) {
        const int s = c_nbr_off[n], e = c_nbr_off[n + 1];
        const float4 bv = make_float4(bi[o0], bi[o0 + 1], bi[o0 + 2], bi[o0 + 3]);
        #pragma unroll
        for (int b = 0; b < TB; b++) {
            float4 a = bv;
            for (int k = s; k < e; k++) {
                const float aw = ae[k];
                const float4 hv = *reinterpret_cast<const float4*>(h + b * STATE + c_nbr_lst[k] * WD + o0);
                a.x = fmaf(aw, hv.x, a.x);
                a.y = fmaf(aw, hv.y, a.y);
                a.z = fmaf(aw, hv.z, a.z);
                a.w = fmaf(aw, hv.w, a.w);
            }
            if (relu) {
                a.x = fmaxf(a.x, 0.f); a.y = fmaxf(a.y, 0.f);
                a.z = fmaxf(a.z, 0.f); a.w = fmaxf(a.w, 0.f);
            }
            *reinterpret_cast<float4*>(dst + b * STATE + n * WD + o0) = a;
        }
    };

    // Hidden-layer per-node matmul, f32x2, bt=6, ot=4.
    // Per chunk: stage acts for 3 batches, load 4 weight rows once, swap act half.
    auto mm64 = [&](const float* __restrict__ src, const float* __restrict__ wgt,
                    float* __restrict__ dst) {
        unsigned long long accL[TB], accH[TB];
        #pragma unroll
        for (int b = 0; b < TB; b++) { accL[b] = 0ull; accH[b] = 0ull; }
        const float* wrow = wgt + n * WD * WD + o0;
        const float* abase = src + n * WD;
        #pragma unroll 2
        for (int i = 0; i < WD; i += 4) {
            const ulonglong2 w0p = __ldg(reinterpret_cast<const ulonglong2*>(wrow + (i + 0) * WD));
            const ulonglong2 w1p = __ldg(reinterpret_cast<const ulonglong2*>(wrow + (i + 1) * WD));
            const ulonglong2 w2p = __ldg(reinterpret_cast<const ulonglong2*>(wrow + (i + 2) * WD));
            const ulonglong2 w3p = __ldg(reinterpret_cast<const ulonglong2*>(wrow + (i + 3) * WD));
            #pragma unroll
            for (int h = 0; h < 2; h++) {        // batch halves: 3 + 3
                float4 xv[3];
                #pragma unroll
                for (int q = 0; q < 3; q++)
                    xv[q] = *reinterpret_cast<const float4*>(abase + (h * 3 + q) * STATE + i);
                #pragma unroll
                for (int q = 0; q < 3; q++) {
                    const int b = h * 3 + q;
                    const unsigned long long x0 = dup2(xv[q].x);
                    fma2(accL[b], x0, w0p.x);
                    fma2(accH[b], x0, w0p.y);
                    const unsigned long long x1 = dup2(xv[q].y);
                    fma2(accL[b], x1, w1p.x);
                    fma2(accH[b], x1, w1p.y);
                    const unsigned long long x2 = dup2(xv[q].z);
                    fma2(accL[b], x2, w2p.x);
                    fma2(accH[b], x2, w2p.y);
                    const unsigned long long x3 = dup2(xv[q].w);
                    fma2(accL[b], x3, w3p.x);
                    fma2(accH[b], x3, w3p.y);
                }
            }
        }
        #pragma unroll
        for (int b = 0; b < TB; b++)
            *reinterpret_cast<ulonglong2*>(dst + b * STATE + n * WD + o0) =
                make_ulonglong2(accL[b], accH[b]);
    };

    agg(bufA, aeff + 0, bias + 0, bufB, true);        // L0 agg
    __syncthreads();
    mm64(bufB, w1, bufA);                              // L1 matmul
    __syncthreads();
    agg(bufA, aeff + 70, bias + WD, bufB, true);       // L1 agg
    __syncthreads();
    mm64(bufB, w2, bufA);                              // L2 matmul
    __syncthreads();
    agg(bufA, aeff + 140, bias + 2 * WD, bufB, true);  // L2 agg
    __syncthreads();

    // ---- Layer 3 matmul: bufB[b][n][0:64] @ w3[n][64][13] -> bufA (stride WD) ----
    if (tid < NN * FOUT) {
        const int n3 = tid / FOUT, o3 = tid - n3 * FOUT;
        float acc[TB];
        #pragma unroll
        for (int b = 0; b < TB; b++) acc[b] = 0.f;
        #pragma unroll 4
        for (int i = 0; i < WD; i++) {
            const float wv = __ldg(w3 + (n3 * WD + i) * FOUT + o3);
            #pragma unroll
            for (int b = 0; b < TB; b++)
                acc[b] = fmaf(bufB[b * STATE + n3 * WD + i], wv, acc[b]);
        }
        #pragma unroll
        for (int b = 0; b < TB; b++)
            bufA[b * STATE + n3 * WD + o3] = acc[b];
    }
    __syncthreads();

    // ---- Layer 3 aggregation + bias, store to global (guarded) ----
    if (tid < NN * FOUT) {
        const int n3 = tid / FOUT, o3 = tid - n3 * FOUT;
        const int s = c_nbr_off[n3], e = c_nbr_off[n3 + 1];
        const float bv3 = bias[3 * WD + o3];
        #pragma unroll
        for (int b = 0; b < TB; b++) {
            float a0 = bv3;
            for (int k = s; k < e; k++)
                a0 = fmaf(aeff[210 + k], bufA[b * STATE + c_nbr_lst[k] * WD + o3], a0);
            if (brow0 + b < B)
                out[(brow0 + b) * (NN * FOUT) + n3 * FOUT + o3] = a0;
        }
    }
}

extern "C" void kernel_launch(void* const* d_in, const int* in_sizes, int n_in,
                              void* d_out, int out_size) {
    const float* x   = (const float*)d_in[0];
    const float* w0  = (const float*)d_in[1];
    const float* w1  = (const float*)d_in[2];
    const float* w2  = (const float*)d_in[3];
    const float* w3  = (const float*)d_in[4];
    const float* aw0 = (const float*)d_in[5];
    const float* aw1 = (const float*)d_in[6];
    const float* aw2 = (const float*)d_in[7];
    const float* aw3 = (const float*)d_in[8];
    const float* b0  = (const float*)d_in[9];
    const float* b1  = (const float*)d_in[10];
    const float* b2  = (const float*)d_in[11];
    const float* b3  = (const float*)d_in[12];
    float* out = (float*)d_out;

    const int B = in_sizes[0] / (NN * FIN);
    const int grid = (B + TB - 1) / TB;
    const size_t smem_bytes =
        (size_t)(2 * TB * STATE + 4 * 70 + 3 * WD + FOUT) * sizeof(float);

    cudaFuncSetAttribute(gnn_fused, cudaFuncAttributeMaxDynamicSharedMemorySize,
                         (int)smem_bytes);
    gnn_fused<<<grid, NT, smem_bytes>>>(x, w0, w1, w2, w3,
                                        aw0, aw1, aw2, aw3,
                                        b0, b1, b2, b3, out, B);
}